// round 3
// baseline (speedup 1.0000x reference)
#include <cuda_runtime.h>
#include <cuda_bf16.h>
#include <cstddef>

#define N_NODES 50000
#define HD      128
#define NB      8
#define NR      16
#define NE      640000

// Scratch (device globals — no allocation allowed in kernel_launch).
__device__ float g_Hb[(size_t)N_NODES * NB * HD];   // 204.8 MB: Hb[n][b*128+o]
__device__ float g_h1[(size_t)N_NODES * HD];        // 25.6 MB: layer-1 output

// ---------------------------------------------------------------------------
// GEMM: Hb[n][b*128+o] = sum_k act(A[n][k]) * basis[b][k][o]
// A: [N,128] row-major, basis: [NB,128,128].
// Block = 256 threads computes a 64(rows) x 128(cols) tile for one basis b.
// ---------------------------------------------------------------------------
template <bool RELU_IN>
__global__ __launch_bounds__(256) void gemm_hb_kernel(
    const float* __restrict__ A, const float* __restrict__ basis,
    float* __restrict__ Hb)
{
    __shared__ float As[64][32];    // 8 KB
    __shared__ float Bs[32][128];   // 16 KB

    const int b   = blockIdx.y;
    const int n0  = blockIdx.x * 64;
    const int tid = threadIdx.x;
    const int cx  = tid & 31;   // column group: cols cx*4 .. cx*4+3
    const int ry  = tid >> 5;   // row group: rows ry*8 .. ry*8+7

    float acc[8][4];
#pragma unroll
    for (int j = 0; j < 8; j++)
#pragma unroll
        for (int q = 0; q < 4; q++) acc[j][q] = 0.f;

    const float* bsrc = basis + (size_t)b * HD * HD;

    for (int k0 = 0; k0 < HD; k0 += 32) {
        // Load A tile: 64 rows x 32 k. 2048 floats / 256 threads = 8 each.
#pragma unroll
        for (int i = 0; i < 8; i++) {
            int e = tid + i * 256;
            int r = e >> 5, c = e & 31;
            int n = n0 + r;
            float v = (n < N_NODES) ? A[(size_t)n * HD + k0 + c] : 0.f;
            if (RELU_IN) v = fmaxf(v, 0.f);
            As[r][c] = v;
        }
        // Load B tile: 32 k x 128 o. 4096 floats / 256 threads = 16 each.
#pragma unroll
        for (int i = 0; i < 16; i++) {
            int e  = tid + i * 256;
            int kk = e >> 7, o = e & 127;
            Bs[kk][o] = bsrc[(size_t)(k0 + kk) * HD + o];
        }
        __syncthreads();

#pragma unroll 8
        for (int kk = 0; kk < 32; kk++) {
            float4 b4 = *reinterpret_cast<const float4*>(&Bs[kk][cx * 4]);
#pragma unroll
            for (int j = 0; j < 8; j++) {
                float a = As[ry * 8 + j][kk];   // broadcast within warp
                acc[j][0] = fmaf(a, b4.x, acc[j][0]);
                acc[j][1] = fmaf(a, b4.y, acc[j][1]);
                acc[j][2] = fmaf(a, b4.z, acc[j][2]);
                acc[j][3] = fmaf(a, b4.w, acc[j][3]);
            }
        }
        __syncthreads();
    }

#pragma unroll
    for (int j = 0; j < 8; j++) {
        int n = n0 + ry * 8 + j;
        if (n < N_NODES) {
            float4 v = make_float4(acc[j][0], acc[j][1], acc[j][2], acc[j][3]);
            *reinterpret_cast<float4*>(
                &Hb[(size_t)n * (NB * HD) + b * HD + cx * 4]) = v;
        }
    }
}

// ---------------------------------------------------------------------------
// out[n][o] = bias[o]  (initialize accumulation target)
// ---------------------------------------------------------------------------
__global__ void init_bias_kernel(float* __restrict__ out,
                                 const float* __restrict__ bias)
{
    int idx = blockIdx.x * blockDim.x + threadIdx.x;
    if (idx < N_NODES * HD) out[idx] = bias[idx & (HD - 1)];
}

// ---------------------------------------------------------------------------
// Edge kernel: one warp per edge.
//   acc[o] = sum_b coef[et][b] * Hb[src][b*128+o]
//   atomicAdd(out[dst][o], acc[o]*norm)
// Lane handles outputs o = lane*4 .. lane*4+3 (float4 gather: 4 KB contiguous
// per edge from Hb's [n][b][o] layout).
// ---------------------------------------------------------------------------
__global__ __launch_bounds__(256) void edge_kernel(
    const float* __restrict__ Hb, const float* __restrict__ coef,
    const float* __restrict__ norm, const int* __restrict__ src,
    const int* __restrict__ dst, const int* __restrict__ et,
    float* __restrict__ out)
{
    int warp = blockIdx.x * (blockDim.x >> 5) + (threadIdx.x >> 5);
    int lane = threadIdx.x & 31;
    if (warp >= NE) return;

    int   s  = __ldg(&src[warp]);
    int   d  = __ldg(&dst[warp]);
    int   r  = __ldg(&et[warp]);
    float nm = __ldg(&norm[warp]);

    const float* hp = Hb + (size_t)s * (NB * HD) + lane * 4;

    float ax = 0.f, ay = 0.f, az = 0.f, aw = 0.f;
#pragma unroll
    for (int b = 0; b < NB; b++) {
        float  c = __ldg(&coef[r * NB + b]);
        float4 v = *reinterpret_cast<const float4*>(hp + b * HD);
        ax = fmaf(c, v.x, ax);
        ay = fmaf(c, v.y, ay);
        az = fmaf(c, v.z, az);
        aw = fmaf(c, v.w, aw);
    }

    float* op = out + (size_t)d * HD + lane * 4;
    atomicAdd(op + 0, ax * nm);
    atomicAdd(op + 1, ay * nm);
    atomicAdd(op + 2, az * nm);
    atomicAdd(op + 3, aw * nm);
}

// ---------------------------------------------------------------------------
// In-place ReLU
// ---------------------------------------------------------------------------
__global__ void relu_kernel(float* __restrict__ x)
{
    int idx = blockIdx.x * blockDim.x + threadIdx.x;
    if (idx < N_NODES * HD) x[idx] = fmaxf(x[idx], 0.f);
}

// ---------------------------------------------------------------------------
// kernel_launch
// Inputs: 0:h 1:norm 2:src 3:dst 4:etype 5:V1 6:coef1 7:bias1 8:V2 9:coef2 10:bias2
// ---------------------------------------------------------------------------
extern "C" void kernel_launch(void* const* d_in, const int* in_sizes, int n_in,
                              void* d_out, int out_size)
{
    const float* h     = (const float*)d_in[0];
    const float* norm  = (const float*)d_in[1];
    const int*   src   = (const int*)d_in[2];
    const int*   dst   = (const int*)d_in[3];
    const int*   etype = (const int*)d_in[4];
    const float* V1    = (const float*)d_in[5];
    const float* coef1 = (const float*)d_in[6];
    const float* bias1 = (const float*)d_in[7];
    const float* V2    = (const float*)d_in[8];
    const float* coef2 = (const float*)d_in[9];
    const float* bias2 = (const float*)d_in[10];
    float*       out   = (float*)d_out;

    float* Hb;  cudaGetSymbolAddress((void**)&Hb, g_Hb);
    float* h1;  cudaGetSymbolAddress((void**)&h1, g_h1);

    dim3 gemm_grid((N_NODES + 63) / 64, NB);
    int  nh_elems   = N_NODES * HD;
    int  elem_grid  = (nh_elems + 255) / 256;
    int  edge_grid  = (NE + 7) / 8;   // 8 warps (edges) per 256-thread block

    // ---- Layer 1: h1 = relu(scatter(gather(h @ V1) * coef1 * norm) + bias1)
    gemm_hb_kernel<false><<<gemm_grid, 256>>>(h, V1, Hb);
    init_bias_kernel<<<elem_grid, 256>>>(h1, bias1);
    edge_kernel<<<edge_grid, 256>>>(Hb, coef1, norm, src, dst, etype, h1);
    relu_kernel<<<elem_grid, 256>>>(h1);

    // ---- Layer 2: out = scatter(gather(h1 @ V2) * coef2 * norm) + bias2
    gemm_hb_kernel<false><<<gemm_grid, 256>>>(h1, V2, Hb);
    init_bias_kernel<<<elem_grid, 256>>>(out, bias2);
    edge_kernel<<<edge_grid, 256>>>(Hb, coef2, norm, src, dst, etype, out);
}